// round 8
// baseline (speedup 1.0000x reference)
#include <cuda_runtime.h>
#include <cuda_fp16.h>
#include <cstdint>

#define TT        10
#define NB        32                 // batch rows per CTA
#define THREADS   512
#define NCTA      (65536 / NB)       // 2048

// smem layout (bytes)
#define XH_OFF    0                  // x hi: 512 k-rows x 32 n x 2B = 32KB
#define XL_OFF    32768
#define AY_OFF    65536              // Ay: per-thread 33-float padded rows
#define SMEM_TOTAL (65536 + 512 * 33 * 4)   // 133120

// W in MMA-fragment order: uint4 index ((chunk16*32 + mtile)*32 + lane),
// halfs within = {a0..a7} of mma.m16n8k16 A fragment.
__device__ __half g_WbH[262144];   // 512KB  (32 chunks)
__device__ __half g_WbL[262144];
__device__ __half g_WaH[131072];   // 256KB  (16 chunks)
__device__ __half g_WaL[131072];

// ---------------- PTX helpers ----------------
static __device__ __forceinline__ uint32_t smem_u32(const void* p) {
    uint32_t a;
    asm("{ .reg .u64 t; cvta.to.shared.u64 t, %1; cvt.u32.u64 %0, t; }" : "=r"(a) : "l"(p));
    return a;
}
static __device__ __forceinline__ void ldmB4(uint32_t* r, uint32_t addr) {
    asm volatile("ldmatrix.sync.aligned.m8n8.x4.trans.shared.b16 {%0,%1,%2,%3}, [%4];"
                 : "=r"(r[0]), "=r"(r[1]), "=r"(r[2]), "=r"(r[3]) : "r"(addr));
}
static __device__ __forceinline__ void mma16816(float* d, const uint32_t* a, const uint32_t* b) {
    asm volatile("mma.sync.aligned.m16n8k16.row.col.f32.f16.f16.f32 "
                 "{%0,%1,%2,%3}, {%4,%5,%6,%7}, {%8,%9}, {%0,%1,%2,%3};"
                 : "+f"(d[0]), "+f"(d[1]), "+f"(d[2]), "+f"(d[3])
                 : "r"(a[0]), "r"(a[1]), "r"(a[2]), "r"(a[3]), "r"(b[0]), "r"(b[1]));
}
static __device__ __forceinline__ void mma16816h(uint32_t* c, const uint32_t* a, const uint32_t* b) {
    asm volatile("mma.sync.aligned.m16n8k16.row.col.f16.f16.f16.f16 "
                 "{%0,%1}, {%2,%3,%4,%5}, {%6,%7}, {%0,%1};"
                 : "+r"(c[0]), "+r"(c[1])
                 : "r"(a[0]), "r"(a[1]), "r"(a[2]), "r"(a[3]), "r"(b[0]), "r"(b[1]));
}

// Swizzle for 64B rows (x planes): XOR 16B-slot bits [5:4] with row bits [2:1].
static __device__ __host__ __forceinline__ uint32_t swz64(int row, int colbyte) {
    return (uint32_t)(row * 64 + (colbyte ^ ((row & 6) << 3)));
}

// ---------------- prep: expand complex A,B -> fp16 hi/lo FRAGMENT-ORDER arrays ----------------
__global__ void prep_kernel(const float* __restrict__ A, const float* __restrict__ B) {
    const int NBEL = 512 * 512, NAEL = 512 * 256;
    for (int i = blockIdx.x * blockDim.x + threadIdx.x; i < NBEL + NAEL;
         i += gridDim.x * blockDim.x) {
        float v;
        __half *dH, *dL;
        int p, k;
        if (i < NBEL) {
            p = i >> 9; k = i & 511;
            if (k < 256) v = (p < 256) ? B[p * 256 + k] : B[65536 + (p - 256) * 256 + k];
            else { int q = k - 256; v = (p < 256) ? -B[65536 + p * 256 + q] : B[(p - 256) * 256 + q]; }
            dH = g_WbH; dL = g_WbL;
        } else {
            int j = i - NBEL;
            p = j >> 8; k = j & 255;
            if (k < 128) v = (p < 256) ? A[p * 128 + k] : A[32768 + (p - 256) * 128 + k];
            else { int q = k - 128; v = (p < 256) ? -A[32768 + p * 128 + q] : A[(p - 256) * 128 + q]; }
            dH = g_WaH; dL = g_WaL;
        }
        // fragment-order destination
        const int chunk = k >> 4, kk = k & 15, mt = p >> 4, row = p & 15;
        const int rr = (row >= 8 ? 1 : 0) + (kk >= 8 ? 2 : 0);
        const int t = (kk & 7) >> 1, pos = kk & 1;
        const int lane = (row & 7) * 4 + t;
        const int dest = ((chunk * 32 + mt) * 32 + lane) * 8 + rr * 2 + pos;
        __half hi = __float2half_rn(v);
        dH[dest] = hi;
        dL[dest] = __float2half_rn(v - __half2float(hi));
    }
}

// load A fragments (H mt0, H mt1, L mt0, L mt1) for one K16 chunk
static __device__ __forceinline__ void ldA(uint4* Ar, const uint4* gH, const uint4* gL, int idx) {
    Ar[0] = __ldg(gH + idx);
    Ar[1] = __ldg(gH + idx + 32);
    Ar[2] = __ldg(gL + idx);
    Ar[3] = __ldg(gL + idx + 32);
}

// ---------------- epilogue slice ----------------
struct EpiArgs {
    const float (*d)[4];   // 4 accs of the half being epilogued
    float* ayrow;          // &ays[tid*33]
    char* smc;
    float g, e;
    int mbase, eg, ec;
    uint32_t exor;
    int half;              // n-half being epilogued (0 or 1)
    bool first;            // pass-0 math (x0 = shrink(g*Ay)), also stores Ay
};

static __device__ __forceinline__ void epi_iter(const EpiArgs& a, int j) {
    const int mt = j >> 2, nt = (j >> 1) & 1, rg = j & 1;
    const int p = a.mbase + mt * 16 + a.eg + rg * 8;
    const uint32_t off = (uint32_t)p * 64
        + (((uint32_t)((a.half * 16 + nt * 8) * 2 + 4 * a.ec)) ^ a.exor);
    const int ai = mt * 2 + nt;
    const int r = (mt * 4 + a.half * 2 + nt) * 4 + rg * 2;
    float v0, v1;
    if (a.first) {
        const float ay0 = a.d[ai][rg * 2 + 0], ay1 = a.d[ai][rg * 2 + 1];
        a.ayrow[r] = ay0; a.ayrow[r + 1] = ay1;
        v0 = a.g * ay0;
        v1 = a.g * ay1;
    } else {
        const float ay0 = a.ayrow[r], ay1 = a.ayrow[r + 1];
        __half2 hh = *(const __half2*)(a.smc + XH_OFF + off);
        __half2 ll = *(const __half2*)(a.smc + XL_OFF + off);
        float2 fh = __half22float2(hh), fl = __half22float2(ll);
        v0 = fmaf(a.g, ay0 - a.d[ai][rg * 2 + 0], fh.x + fl.x);
        v1 = fmaf(a.g, ay1 - a.d[ai][rg * 2 + 1], fh.y + fl.y);
    }
    float x0 = copysignf(fmaxf(fabsf(v0) - a.e, 0.0f), v0);
    float x1 = copysignf(fmaxf(fabsf(v1) - a.e, 0.0f), v1);
    __half h0 = __float2half_rn(x0), h1 = __float2half_rn(x1);
    __half l0 = __float2half_rn(x0 - __half2float(h0));
    __half l1 = __float2half_rn(x1 - __half2float(h1));
    *(__half2*)(a.smc + XH_OFF + off) = __halves2half2(h0, h1);
    *(__half2*)(a.smc + XL_OFF + off) = __halves2half2(l0, l1);
}

// ---------------- half-sweep: full K, one n-half; epilogue slices interleaved ----------------
// acc[4][4]: accs for this half (mt 0..1 x nt 0..1). Zeroed here.
template <int NC, bool EPI>
static __device__ __forceinline__ void sweep(
    char* smc, const __half* gHh, const __half* gLh,
    float (*acc)[4], int mt0, int lane, int half, const EpiArgs* ea)
{
    const uint4* gH = (const uint4*)gHh;
    const uint4* gL = (const uint4*)gLh;
    const uint32_t smb = smem_u32(smc);
    const uint32_t bxor = (uint32_t)((lane & 6) << 3);
    const uint32_t brow = ((uint32_t)(lane & 7) + ((uint32_t)((lane >> 3) & 1)) * 8) * 64;
    const uint32_t bcol = ((uint32_t)(half * 32) + ((uint32_t)(lane >> 4) * 16)) ^ bxor;

#pragma unroll
    for (int i = 0; i < 4; ++i)
#pragma unroll
        for (int j = 0; j < 4; ++j) acc[i][j] = 0.0f;
    uint32_t cacc[4][2];
#pragma unroll
    for (int i = 0; i < 4; ++i) { cacc[i][0] = 0u; cacc[i][1] = 0u; }

    const int idx = mt0 * 32 + lane;
    uint4 A0[4], A1[4];
    ldA(A0, gH, gL, idx);
    ldA(A1, gH, gL, idx + 1024);

#pragma unroll 1
    for (int c = 0; c < NC; c += 2) {
        if (EPI && (c & (NC / 8 - 1)) == 0) epi_iter(*ea, c / (NC / 8));
        // ---- even chunk c : uses A0 ----
        {
            const uint32_t xrow = smb + ((uint32_t)c << 10) + brow;
            uint32_t bh[4], bl[4];
            ldmB4(bh, xrow + bcol);
            ldmB4(bl, xrow + 32768u + bcol);
            const uint32_t* ah0 = (const uint32_t*)&A0[0];
            const uint32_t* ah1 = (const uint32_t*)&A0[1];
            const uint32_t* al0 = (const uint32_t*)&A0[2];
            const uint32_t* al1 = (const uint32_t*)&A0[3];
#pragma unroll
            for (int nt = 0; nt < 2; ++nt) {
                mma16816(acc[nt],     ah0, &bh[nt * 2]);
                mma16816(acc[2 + nt], ah1, &bh[nt * 2]);
            }
#pragma unroll
            for (int nt = 0; nt < 2; ++nt) {
                mma16816h(cacc[nt],     ah0, &bl[nt * 2]);
                mma16816h(cacc[2 + nt], ah1, &bl[nt * 2]);
            }
#pragma unroll
            for (int nt = 0; nt < 2; ++nt) {
                mma16816h(cacc[nt],     al0, &bh[nt * 2]);
                mma16816h(cacc[2 + nt], al1, &bh[nt * 2]);
            }
        }
        if (c + 2 < NC) ldA(A0, gH, gL, idx + (c + 2) * 1024);
        // ---- odd chunk c+1 : uses A1 ----
        {
            const uint32_t xrow = smb + ((uint32_t)(c + 1) << 10) + brow;
            uint32_t bh[4], bl[4];
            ldmB4(bh, xrow + bcol);
            ldmB4(bl, xrow + 32768u + bcol);
            const uint32_t* ah0 = (const uint32_t*)&A1[0];
            const uint32_t* ah1 = (const uint32_t*)&A1[1];
            const uint32_t* al0 = (const uint32_t*)&A1[2];
            const uint32_t* al1 = (const uint32_t*)&A1[3];
#pragma unroll
            for (int nt = 0; nt < 2; ++nt) {
                mma16816(acc[nt],     ah0, &bh[nt * 2]);
                mma16816(acc[2 + nt], ah1, &bh[nt * 2]);
            }
#pragma unroll
            for (int nt = 0; nt < 2; ++nt) {
                mma16816h(cacc[nt],     ah0, &bl[nt * 2]);
                mma16816h(cacc[2 + nt], ah1, &bl[nt * 2]);
            }
#pragma unroll
            for (int nt = 0; nt < 2; ++nt) {
                mma16816h(cacc[nt],     al0, &bh[nt * 2]);
                mma16816h(cacc[2 + nt], al1, &bh[nt * 2]);
            }
        }
        if (c + 3 < NC) ldA(A1, gH, gL, idx + (c + 3) * 1024);
    }

    // fold fp16 corrections into fp32 accumulators
#pragma unroll
    for (int i = 0; i < 4; ++i) {
        float2 f0 = __half22float2(*(const __half2*)&cacc[i][0]);
        float2 f1 = __half22float2(*(const __half2*)&cacc[i][1]);
        acc[i][0] += f0.x; acc[i][1] += f0.y;
        acc[i][2] += f1.x; acc[i][3] += f1.y;
    }
}

// ---------------- main fused kernel ----------------
__global__ __launch_bounds__(THREADS, 1)
void lista_main(const float* __restrict__ y,
                const float* __restrict__ etas,
                const float* __restrict__ gammas,
                float* __restrict__ out) {
    extern __shared__ char smc[];
    const int tid = threadIdx.x, lane = tid & 31, wid = tid >> 5;
    const int mbase = wid * 32;               // 16 M-warps x 32 rows
    const int mt0 = wid * 2;                  // first mtile index
    const long b0 = (long)blockIdx.x * NB;
    float* ays = (float*)(smc + AY_OFF);

    // stage y into x planes (rows 0..255): k = c*128 + q
    for (int idx = tid; idx < NB * 256; idx += THREADS) {
        int n = idx >> 8, j = idx & 255, q = j >> 1, cc = j & 1, k = cc * 128 + q;
        float v = y[(b0 + n) * 256 + j];
        __half hi = __float2half_rn(v);
        __half lo = __float2half_rn(v - __half2float(hi));
        uint32_t off = swz64(k, n * 2);
        *(__half*)(smc + XH_OFF + off) = hi;
        *(__half*)(smc + XL_OFF + off) = lo;
    }
    __syncthreads();

    // epilogue lane geometry
    const int eg = lane >> 2, ec = lane & 3;
    const uint32_t exor = (uint32_t)((eg & 6) << 3);

    float acc0[4][4], acc1[4][4];
    EpiArgs ea;
    ea.ayrow = ays + tid * 33;
    ea.smc = smc;
    ea.mbase = mbase; ea.eg = eg; ea.ec = ec; ea.exor = exor;

    // -------- pass 0: Ay = Wa * y --------
    sweep<16, false>(smc, g_WaH, g_WaL, acc0, mt0, lane, 0, nullptr);
    __syncthreads();
    ea.d = acc0; ea.g = gammas[0]; ea.e = etas[0]; ea.half = 0; ea.first = true;
    sweep<16, true>(smc, g_WaH, g_WaL, acc1, mt0, lane, 1, &ea);
    __syncthreads();

    // -------- passes 1..TT --------
#pragma unroll 1
    for (int t = 1; t <= TT; ++t) {
        // h0 sweep of pass t, interleaving epilogue of h1(pass t-1)
        ea.d = acc1; ea.g = gammas[t - 1]; ea.e = etas[t - 1];
        ea.half = 1; ea.first = (t == 1);
        sweep<32, true>(smc, g_WbH, g_WbL, acc0, mt0, lane, 0, &ea);
        __syncthreads();
        // h1 sweep of pass t, interleaving epilogue of h0(pass t)
        ea.d = acc0; ea.g = gammas[t]; ea.e = etas[t];
        ea.half = 0; ea.first = false;
        sweep<32, true>(smc, g_WbH, g_WbL, acc1, mt0, lane, 1, &ea);
        __syncthreads();
    }

    // tail: epilogue of h1(pass TT)
    ea.d = acc1; ea.g = gammas[TT]; ea.e = etas[TT]; ea.half = 1; ea.first = false;
#pragma unroll
    for (int j = 0; j < 8; ++j) epi_iter(ea, j);
    __syncthreads();

    // output: out[b][m][c] = x[p = c*256 + m], coalesced fp32 writes
    for (int idx = tid; idx < NB * 512; idx += THREADS) {
        const int n = idx >> 9, i = idx & 511, m = i >> 1, cc = i & 1;
        const int p = cc * 256 + m;
        const uint32_t off = swz64(p, n * 2);
        const float v = __half2float(*(const __half*)(smc + XH_OFF + off))
                      + __half2float(*(const __half*)(smc + XL_OFF + off));
        out[(b0 + n) * 512 + i] = v;
    }
}

extern "C" void kernel_launch(void* const* d_in, const int* in_sizes, int n_in,
                              void* d_out, int out_size) {
    const float* y      = (const float*)d_in[0];
    const float* A      = (const float*)d_in[1];
    const float* B      = (const float*)d_in[2];
    const float* etas   = (const float*)d_in[3];
    const float* gammas = (const float*)d_in[4];
    float* out = (float*)d_out;

    prep_kernel<<<512, 256>>>(A, B);

    cudaFuncSetAttribute(lista_main, cudaFuncAttributeMaxDynamicSharedMemorySize, SMEM_TOTAL);
    lista_main<<<NCTA, THREADS, SMEM_TOTAL>>>(y, etas, gammas, out);
}

// round 9
// speedup vs baseline: 1.1833x; 1.1833x over previous
#include <cuda_runtime.h>
#include <cuda_fp16.h>
#include <cstdint>

#define TT        10
#define NB        32                 // batch rows per CTA
#define THREADS   512
#define NCTA      (65536 / NB)       // 2048

// smem layout (bytes): two x-plane buffers, each = XH(32KB) + XL(32KB)
#define XBUF(b)   ((uint32_t)(b) * 65536u)
#define XL_REL    32768u
#define AY_OFF    131072             // Ay: per-thread 33-float padded rows
#define SMEM_TOTAL (131072 + 512 * 33 * 4)   // 198656

// W in MMA-fragment order: uint4 index ((chunk16*32 + mtile)*32 + lane),
// halfs within = {a0..a7} of mma.m16n8k16 A fragment.
__device__ __half g_WbH[262144];   // 512KB  (32 chunks)
__device__ __half g_WbL[262144];
__device__ __half g_WaH[131072];   // 256KB  (16 chunks)
__device__ __half g_WaL[131072];

// ---------------- PTX helpers ----------------
static __device__ __forceinline__ uint32_t smem_u32(const void* p) {
    uint32_t a;
    asm("{ .reg .u64 t; cvta.to.shared.u64 t, %1; cvt.u32.u64 %0, t; }" : "=r"(a) : "l"(p));
    return a;
}
static __device__ __forceinline__ void ldmB4(uint32_t* r, uint32_t addr) {
    asm volatile("ldmatrix.sync.aligned.m8n8.x4.trans.shared.b16 {%0,%1,%2,%3}, [%4];"
                 : "=r"(r[0]), "=r"(r[1]), "=r"(r[2]), "=r"(r[3]) : "r"(addr));
}
static __device__ __forceinline__ void mma16816(float* d, const uint32_t* a, const uint32_t* b) {
    asm volatile("mma.sync.aligned.m16n8k16.row.col.f32.f16.f16.f32 "
                 "{%0,%1,%2,%3}, {%4,%5,%6,%7}, {%8,%9}, {%0,%1,%2,%3};"
                 : "+f"(d[0]), "+f"(d[1]), "+f"(d[2]), "+f"(d[3])
                 : "r"(a[0]), "r"(a[1]), "r"(a[2]), "r"(a[3]), "r"(b[0]), "r"(b[1]));
}
static __device__ __forceinline__ void mma16816h(uint32_t* c, const uint32_t* a, const uint32_t* b) {
    asm volatile("mma.sync.aligned.m16n8k16.row.col.f16.f16.f16.f16 "
                 "{%0,%1}, {%2,%3,%4,%5}, {%6,%7}, {%0,%1};"
                 : "+r"(c[0]), "+r"(c[1])
                 : "r"(a[0]), "r"(a[1]), "r"(a[2]), "r"(a[3]), "r"(b[0]), "r"(b[1]));
}

// Swizzle for 64B rows (x planes): XOR 16B-slot bits [5:4] with row bits [2:1].
static __device__ __host__ __forceinline__ uint32_t swz64(int row, int colbyte) {
    return (uint32_t)(row * 64 + (colbyte ^ ((row & 6) << 3)));
}

// ---------------- prep: expand complex A,B -> fp16 hi/lo FRAGMENT-ORDER arrays ----------------
__global__ void prep_kernel(const float* __restrict__ A, const float* __restrict__ B) {
    const int NBEL = 512 * 512, NAEL = 512 * 256;
    for (int i = blockIdx.x * blockDim.x + threadIdx.x; i < NBEL + NAEL;
         i += gridDim.x * blockDim.x) {
        float v;
        __half *dH, *dL;
        int p, k;
        if (i < NBEL) {
            p = i >> 9; k = i & 511;
            if (k < 256) v = (p < 256) ? B[p * 256 + k] : B[65536 + (p - 256) * 256 + k];
            else { int q = k - 256; v = (p < 256) ? -B[65536 + p * 256 + q] : B[(p - 256) * 256 + q]; }
            dH = g_WbH; dL = g_WbL;
        } else {
            int j = i - NBEL;
            p = j >> 8; k = j & 255;
            if (k < 128) v = (p < 256) ? A[p * 128 + k] : A[32768 + (p - 256) * 128 + k];
            else { int q = k - 128; v = (p < 256) ? -A[32768 + p * 128 + q] : A[(p - 256) * 128 + q]; }
            dH = g_WaH; dL = g_WaL;
        }
        // fragment-order destination
        const int chunk = k >> 4, kk = k & 15, mt = p >> 4, row = p & 15;
        const int rr = (row >= 8 ? 1 : 0) + (kk >= 8 ? 2 : 0);
        const int t = (kk & 7) >> 1, pos = kk & 1;
        const int lane = (row & 7) * 4 + t;
        const int dest = ((chunk * 32 + mt) * 32 + lane) * 8 + rr * 2 + pos;
        __half hi = __float2half_rn(v);
        dH[dest] = hi;
        dL[dest] = __float2half_rn(v - __half2float(hi));
    }
}

// load A fragments (H mt0, H mt1, L mt0, L mt1) for one K16 chunk
static __device__ __forceinline__ void ldA(uint4* Ar, const uint4* gH, const uint4* gL, int idx) {
    Ar[0] = __ldg(gH + idx);
    Ar[1] = __ldg(gH + idx + 32);
    Ar[2] = __ldg(gL + idx);
    Ar[3] = __ldg(gL + idx + 32);
}

// ---------------- GEMM pass: A from global (fragment LDG), B from x-plane buffer ----------------
static __device__ __forceinline__ void gemm_pass(
    const char* smc, uint32_t xbase, const __half* gHh, const __half* gLh, int NC,
    float (*acc)[4], int mt0, int lane)
{
    const uint4* gH = (const uint4*)gHh;
    const uint4* gL = (const uint4*)gLh;
    const uint32_t smb = smem_u32(smc) + xbase;
    const uint32_t bxor = (uint32_t)((lane & 6) << 3);
    const uint32_t brow = ((uint32_t)(lane & 7) + ((uint32_t)((lane >> 3) & 1)) * 8) * 64;
    const uint32_t bcol0 = (((uint32_t)(lane >> 4) * 16)) ^ bxor;        // n 0..15
    const uint32_t bcol1 = (32u + (uint32_t)(lane >> 4) * 16) ^ bxor;    // n 16..31

    uint32_t cacc[8][2];
#pragma unroll
    for (int i = 0; i < 8; ++i) { cacc[i][0] = 0u; cacc[i][1] = 0u; }

    const int idx = mt0 * 32 + lane;
    uint4 A0[4], A1[4];
    ldA(A0, gH, gL, idx);
    ldA(A1, gH, gL, idx + 1024);

#pragma unroll 1
    for (int c = 0; c < NC; c += 2) {
        // ---- even chunk c : uses A0 ----
        {
            const uint32_t xrow = smb + ((uint32_t)c << 10) + brow;
            uint32_t bh[8], bl[8];
            ldmB4(bh,     xrow + bcol0);
            ldmB4(bh + 4, xrow + bcol1);
            ldmB4(bl,     xrow + XL_REL + bcol0);
            ldmB4(bl + 4, xrow + XL_REL + bcol1);
            const uint32_t* ah0 = (const uint32_t*)&A0[0];
            const uint32_t* ah1 = (const uint32_t*)&A0[1];
            const uint32_t* al0 = (const uint32_t*)&A0[2];
            const uint32_t* al1 = (const uint32_t*)&A0[3];
#pragma unroll
            for (int nt = 0; nt < 4; ++nt) {
                mma16816(acc[nt],     ah0, &bh[nt * 2]);
                mma16816(acc[4 + nt], ah1, &bh[nt * 2]);
            }
#pragma unroll
            for (int nt = 0; nt < 4; ++nt) {
                mma16816h(cacc[nt],     ah0, &bl[nt * 2]);
                mma16816h(cacc[4 + nt], ah1, &bl[nt * 2]);
            }
#pragma unroll
            for (int nt = 0; nt < 4; ++nt) {
                mma16816h(cacc[nt],     al0, &bh[nt * 2]);
                mma16816h(cacc[4 + nt], al1, &bh[nt * 2]);
            }
        }
        if (c + 2 < NC) ldA(A0, gH, gL, idx + (c + 2) * 1024);
        // ---- odd chunk c+1 : uses A1 ----
        {
            const uint32_t xrow = smb + ((uint32_t)(c + 1) << 10) + brow;
            uint32_t bh[8], bl[8];
            ldmB4(bh,     xrow + bcol0);
            ldmB4(bh + 4, xrow + bcol1);
            ldmB4(bl,     xrow + XL_REL + bcol0);
            ldmB4(bl + 4, xrow + XL_REL + bcol1);
            const uint32_t* ah0 = (const uint32_t*)&A1[0];
            const uint32_t* ah1 = (const uint32_t*)&A1[1];
            const uint32_t* al0 = (const uint32_t*)&A1[2];
            const uint32_t* al1 = (const uint32_t*)&A1[3];
#pragma unroll
            for (int nt = 0; nt < 4; ++nt) {
                mma16816(acc[nt],     ah0, &bh[nt * 2]);
                mma16816(acc[4 + nt], ah1, &bh[nt * 2]);
            }
#pragma unroll
            for (int nt = 0; nt < 4; ++nt) {
                mma16816h(cacc[nt],     ah0, &bl[nt * 2]);
                mma16816h(cacc[4 + nt], ah1, &bl[nt * 2]);
            }
#pragma unroll
            for (int nt = 0; nt < 4; ++nt) {
                mma16816h(cacc[nt],     al0, &bh[nt * 2]);
                mma16816h(cacc[4 + nt], al1, &bh[nt * 2]);
            }
        }
        if (c + 3 < NC) ldA(A1, gH, gL, idx + (c + 3) * 1024);
    }

    // fold fp16 corrections into fp32 accumulators
#pragma unroll
    for (int i = 0; i < 8; ++i) {
        float2 f0 = __half22float2(*(const __half2*)&cacc[i][0]);
        float2 f1 = __half22float2(*(const __half2*)&cacc[i][1]);
        acc[i][0] += f0.x; acc[i][1] += f0.y;
        acc[i][2] += f1.x; acc[i][3] += f1.y;
    }
}

// ---------------- main fused kernel ----------------
__global__ __launch_bounds__(THREADS, 1)
void lista_main(const float* __restrict__ y,
                const float* __restrict__ etas,
                const float* __restrict__ gammas,
                float* __restrict__ out) {
    extern __shared__ char smc[];
    const int tid = threadIdx.x, lane = tid & 31, wid = tid >> 5;
    const int mbase = wid * 32;               // 16 M-warps x 32 rows, full N=32
    const int mt0 = wid * 2;                  // first mtile index
    const long b0 = (long)blockIdx.x * NB;
    float* ays = (float*)(smc + AY_OFF);

    // stage y into buffer 0 (rows 0..255): k = c*128 + q
    for (int idx = tid; idx < NB * 256; idx += THREADS) {
        int n = idx >> 8, j = idx & 255, q = j >> 1, cc = j & 1, k = cc * 128 + q;
        float v = y[(b0 + n) * 256 + j];
        __half hi = __float2half_rn(v);
        __half lo = __float2half_rn(v - __half2float(hi));
        uint32_t off = swz64(k, n * 2);
        *(__half*)(smc + off) = hi;
        *(__half*)(smc + XL_REL + off) = lo;
    }
    __syncthreads();

    float d[8][4];

    // epilogue lane geometry
    const int eg = lane >> 2, ec = lane & 3;
    const uint32_t exor = (uint32_t)((eg & 6) << 3);

    // -------- pass 0: Ay = Wa * y (read buf0, write buf1) --------
#pragma unroll
    for (int i = 0; i < 8; ++i)
#pragma unroll
        for (int j = 0; j < 4; ++j) d[i][j] = 0.0f;
    gemm_pass(smc, XBUF(0), g_WaH, g_WaL, 16, d, mt0, lane);
    {
        const float g = gammas[0], e = etas[0];
        char* xwr = smc + XBUF(1);
#pragma unroll
        for (int mt = 0; mt < 2; ++mt)
#pragma unroll
            for (int nt = 0; nt < 4; ++nt)
#pragma unroll
                for (int rg = 0; rg < 2; ++rg) {
                    const int p = mbase + mt * 16 + eg + rg * 8;
                    const uint32_t off = (uint32_t)p * 64
                                       + (((uint32_t)(16 * nt + 4 * ec)) ^ exor);
                    const int ai = mt * 4 + nt;
                    const int r = ai * 4 + rg * 2;
                    ays[tid * 33 + r]     = d[ai][rg * 2 + 0];
                    ays[tid * 33 + r + 1] = d[ai][rg * 2 + 1];
                    float v0 = g * d[ai][rg * 2 + 0];
                    float v1 = g * d[ai][rg * 2 + 1];
                    float x0 = copysignf(fmaxf(fabsf(v0) - e, 0.0f), v0);
                    float x1 = copysignf(fmaxf(fabsf(v1) - e, 0.0f), v1);
                    __half h0 = __float2half_rn(x0), h1 = __float2half_rn(x1);
                    __half l0 = __float2half_rn(x0 - __half2float(h0));
                    __half l1 = __float2half_rn(x1 - __half2float(h1));
                    *(__half2*)(xwr + off) = __halves2half2(h0, h1);
                    *(__half2*)(xwr + XL_REL + off) = __halves2half2(l0, l1);
                }
    }
    __syncthreads();

    // -------- 10 iterations: pass t reads buf (t&1), writes buf 1-(t&1) --------
#pragma unroll 1
    for (int t = 1; t <= TT; ++t) {
#pragma unroll
        for (int i = 0; i < 8; ++i)
#pragma unroll
            for (int j = 0; j < 4; ++j) d[i][j] = 0.0f;

        const uint32_t rb = XBUF(t & 1);
        gemm_pass(smc, rb, g_WbH, g_WbL, 32, d, mt0, lane);

        // per-warp epilogue, no barrier: writes go to the inactive buffer
        const float g = gammas[t], e = etas[t];
        char* xrd = smc + rb;
        char* xwr = smc + XBUF(1 - (t & 1));
#pragma unroll
        for (int mt = 0; mt < 2; ++mt)
#pragma unroll
            for (int nt = 0; nt < 4; ++nt)
#pragma unroll
                for (int rg = 0; rg < 2; ++rg) {
                    const int p = mbase + mt * 16 + eg + rg * 8;
                    const uint32_t off = (uint32_t)p * 64
                                       + (((uint32_t)(16 * nt + 4 * ec)) ^ exor);
                    const int ai = mt * 4 + nt;
                    const int r = ai * 4 + rg * 2;
                    const float ay0 = ays[tid * 33 + r];
                    const float ay1 = ays[tid * 33 + r + 1];
                    __half2 hh = *(const __half2*)(xrd + off);
                    __half2 ll = *(const __half2*)(xrd + XL_REL + off);
                    float2 fh = __half22float2(hh), fl = __half22float2(ll);
                    float v0 = fmaf(g, ay0 - d[ai][rg * 2 + 0], fh.x + fl.x);
                    float v1 = fmaf(g, ay1 - d[ai][rg * 2 + 1], fh.y + fl.y);
                    float x0 = copysignf(fmaxf(fabsf(v0) - e, 0.0f), v0);
                    float x1 = copysignf(fmaxf(fabsf(v1) - e, 0.0f), v1);
                    __half h0 = __float2half_rn(x0), h1 = __float2half_rn(x1);
                    __half l0 = __float2half_rn(x0 - __half2float(h0));
                    __half l1 = __float2half_rn(x1 - __half2float(h1));
                    *(__half2*)(xwr + off) = __halves2half2(h0, h1);
                    *(__half2*)(xwr + XL_REL + off) = __halves2half2(l0, l1);
                }
        __syncthreads();
    }

    // output from buffer 1 (epilogue of pass TT=10 wrote buf1):
    // out[b][m][c] = x[p = c*256 + m], coalesced fp32 writes
    const char* xf = smc + XBUF(1);
    for (int idx = tid; idx < NB * 512; idx += THREADS) {
        const int n = idx >> 9, i = idx & 511, m = i >> 1, cc = i & 1;
        const int p = cc * 256 + m;
        const uint32_t off = swz64(p, n * 2);
        const float v = __half2float(*(const __half*)(xf + off))
                      + __half2float(*(const __half*)(xf + XL_REL + off));
        out[(b0 + n) * 512 + i] = v;
    }
}

extern "C" void kernel_launch(void* const* d_in, const int* in_sizes, int n_in,
                              void* d_out, int out_size) {
    const float* y      = (const float*)d_in[0];
    const float* A      = (const float*)d_in[1];
    const float* B      = (const float*)d_in[2];
    const float* etas   = (const float*)d_in[3];
    const float* gammas = (const float*)d_in[4];
    float* out = (float*)d_out;

    prep_kernel<<<512, 256>>>(A, B);

    cudaFuncSetAttribute(lista_main, cudaFuncAttributeMaxDynamicSharedMemorySize, SMEM_TOTAL);
    lista_main<<<NCTA, THREADS, SMEM_TOTAL>>>(y, etas, gammas, out);
}

// round 10
// speedup vs baseline: 1.3175x; 1.1135x over previous
#include <cuda_runtime.h>
#include <cuda_fp16.h>
#include <cstdint>

#define TT        10
#define NB        32
#define THREADS   512
#define NCTA      (65536 / NB)       // 2048

// smem layout (bytes): three x-operand planes (hi 16KB + lo 16KB each)
#define XS_OFF    0                  // xs = xr + xi
#define XI_OFF    32768
#define XR_OFF    65536
#define PL_LO     16384
#define K1_OFF    98304              // k1: 256 x 32 fp32 (col-shifted)
#define K2_OFF    131072
#define AYR_OFF   163840
#define AYI_OFF   196608
#define SMEM_TOTAL 229376            // 224KB

// Gauss-stacked weights, MMA fragment order:
// uint4 index ((chunk16*48 + gmt)*32 + lane); gmt in [0,48): rows 0-255 Br-ish,
// 256-511 (Br+Bi), 512-767 (Bi-Br).  (A analog with K=128.)
__device__ __half g_WBH[196608];   // 384KB (16 chunks x 48 mtiles)
__device__ __half g_WBL[196608];
__device__ __half g_WAH[98304];    // 192KB (8 chunks x 48 mtiles)
__device__ __half g_WAL[98304];

// ---------------- PTX helpers ----------------
static __device__ __forceinline__ uint32_t smem_u32(const void* p) {
    uint32_t a;
    asm("{ .reg .u64 t; cvta.to.shared.u64 t, %1; cvt.u32.u64 %0, t; }" : "=r"(a) : "l"(p));
    return a;
}
static __device__ __forceinline__ void ldmB4(uint32_t* r, uint32_t addr) {
    asm volatile("ldmatrix.sync.aligned.m8n8.x4.trans.shared.b16 {%0,%1,%2,%3}, [%4];"
                 : "=r"(r[0]), "=r"(r[1]), "=r"(r[2]), "=r"(r[3]) : "r"(addr));
}
static __device__ __forceinline__ void mma16816(float* d, const uint32_t* a, const uint32_t* b) {
    asm volatile("mma.sync.aligned.m16n8k16.row.col.f32.f16.f16.f32 "
                 "{%0,%1,%2,%3}, {%4,%5,%6,%7}, {%8,%9}, {%0,%1,%2,%3};"
                 : "+f"(d[0]), "+f"(d[1]), "+f"(d[2]), "+f"(d[3])
                 : "r"(a[0]), "r"(a[1]), "r"(a[2]), "r"(a[3]), "r"(b[0]), "r"(b[1]));
}
static __device__ __forceinline__ void mma16816h(uint32_t* c, const uint32_t* a, const uint32_t* b) {
    asm volatile("mma.sync.aligned.m16n8k16.row.col.f16.f16.f16.f16 "
                 "{%0,%1}, {%2,%3,%4,%5}, {%6,%7}, {%0,%1};"
                 : "+r"(c[0]), "+r"(c[1])
                 : "r"(a[0]), "r"(a[1]), "r"(a[2]), "r"(a[3]), "r"(b[0]), "r"(b[1]));
}
// Swizzle for 64B rows (x planes)
static __device__ __host__ __forceinline__ uint32_t swz64(int row, int colbyte) {
    return (uint32_t)(row * 64 + (colbyte ^ ((row & 6) << 3)));
}
// fp32 scratch column shift (bank spread): word index within a 32-word row
static __device__ __forceinline__ uint32_t scol(int m, int n0) {
    return (uint32_t)((n0 + ((m & 3) << 3)) & 31);
}

// ---------------- prep: Gauss-stacked W', fp16 hi/lo fragment order ----------------
__global__ void prep_kernel(const float* __restrict__ A, const float* __restrict__ B) {
    const int NBEL = 768 * 256, NAEL = 768 * 128;
    for (int i = blockIdx.x * blockDim.x + threadIdx.x; i < NBEL + NAEL;
         i += gridDim.x * blockDim.x) {
        int R, k;
        float w;
        __half *dH, *dL;
        if (i < NBEL) {
            R = i >> 8; k = i & 255;
            const int grp = R >> 8, m = R & 255;
            const float br = B[m * 256 + k], bi = B[65536 + m * 256 + k];
            w = (grp == 0) ? br : ((grp == 1) ? br + bi : bi - br);
            dH = g_WBH; dL = g_WBL;
        } else {
            const int j = i - NBEL;
            R = j >> 7; k = j & 127;
            const int grp = R >> 8, m = R & 255;
            const float ar = A[m * 128 + k], ai = A[32768 + m * 128 + k];
            w = (grp == 0) ? ar : ((grp == 1) ? ar + ai : ai - ar);
            dH = g_WAH; dL = g_WAL;
        }
        const int gmt = R >> 4, row = R & 15, chunk = k >> 4, kk = k & 15;
        const int rr = (row >> 3) | ((kk >> 3) << 1);
        const int t = (kk & 7) >> 1, pos = kk & 1;
        const int lane = (row & 7) * 4 + t;
        const int dest = ((chunk * 48 + gmt) * 32 + lane) * 8 + rr * 2 + pos;
        __half hi = __float2half_rn(w);
        dH[dest] = hi;
        dL[dest] = __float2half_rn(w - __half2float(hi));
    }
}

// ---------------- GEMM sub-sweep: NMT mtiles, A from global, B from one plane ----------------
template <int NMT>
static __device__ __forceinline__ void gemm_sub(
    const char* smc, uint32_t plane, const __half* gHh, const __half* gLh,
    int NC, float (*acc)[4], int gmt0, int lane)
{
    const uint4* gH = (const uint4*)gHh;
    const uint4* gL = (const uint4*)gLh;
    const uint32_t smb = smem_u32(smc) + plane;
    const uint32_t bxor = (uint32_t)((lane & 6) << 3);
    const uint32_t brow = ((uint32_t)(lane & 7) + ((uint32_t)((lane >> 3) & 1)) * 8) * 64;
    const uint32_t bcol0 = (((uint32_t)(lane >> 4) * 16)) ^ bxor;
    const uint32_t bcol1 = (32u + (uint32_t)(lane >> 4) * 16) ^ bxor;
    const int CS = 48 * 32;   // uint4 stride per K16 chunk

#pragma unroll
    for (int i = 0; i < NMT * 4; ++i)
#pragma unroll
        for (int j = 0; j < 4; ++j) acc[i][j] = 0.0f;
    uint32_t cacc[NMT * 4][2];
#pragma unroll
    for (int i = 0; i < NMT * 4; ++i) { cacc[i][0] = 0u; cacc[i][1] = 0u; }

    const int idx = gmt0 * 32 + lane;
    uint4 A0[2 * NMT], A1[2 * NMT];
#pragma unroll
    for (int mt = 0; mt < NMT; ++mt) {
        A0[mt] = __ldg(gH + idx + mt * 32);
        A0[NMT + mt] = __ldg(gL + idx + mt * 32);
        A1[mt] = __ldg(gH + idx + CS + mt * 32);
        A1[NMT + mt] = __ldg(gL + idx + CS + mt * 32);
    }

#pragma unroll 1
    for (int c = 0; c < NC; c += 2) {
#pragma unroll
        for (int half = 0; half < 2; ++half) {
            const uint4* Ar = half ? A1 : A0;
            const uint32_t xrow = smb + ((uint32_t)(c + half) << 10) + brow;
            uint32_t bh[8], bl[8];
            ldmB4(bh,     xrow + bcol0);
            ldmB4(bh + 4, xrow + bcol1);
            ldmB4(bl,     xrow + PL_LO + bcol0);
            ldmB4(bl + 4, xrow + PL_LO + bcol1);
#pragma unroll
            for (int mt = 0; mt < NMT; ++mt)
#pragma unroll
                for (int nt = 0; nt < 4; ++nt)
                    mma16816(acc[mt * 4 + nt], (const uint32_t*)&Ar[mt], &bh[nt * 2]);
#pragma unroll
            for (int mt = 0; mt < NMT; ++mt)
#pragma unroll
                for (int nt = 0; nt < 4; ++nt)
                    mma16816h(cacc[mt * 4 + nt], (const uint32_t*)&Ar[mt], &bl[nt * 2]);
#pragma unroll
            for (int mt = 0; mt < NMT; ++mt)
#pragma unroll
                for (int nt = 0; nt < 4; ++nt)
                    mma16816h(cacc[mt * 4 + nt], (const uint32_t*)&Ar[NMT + mt], &bh[nt * 2]);
            // prefetch this buffer's next chunk
            const int pf = c + half + 2;
            if (pf < NC) {
                uint4* Aw = half ? A1 : A0;
#pragma unroll
                for (int mt = 0; mt < NMT; ++mt) {
                    Aw[mt] = __ldg(gH + idx + pf * CS + mt * 32);
                    Aw[NMT + mt] = __ldg(gL + idx + pf * CS + mt * 32);
                }
            }
        }
    }
#pragma unroll
    for (int i = 0; i < NMT * 4; ++i) {
        float2 f0 = __half22float2(*(const __half2*)&cacc[i][0]);
        float2 f1 = __half22float2(*(const __half2*)&cacc[i][1]);
        acc[i][0] += f0.x; acc[i][1] += f0.y;
        acc[i][2] += f1.x; acc[i][3] += f1.y;
    }
}

// split-and-store fp16 hi/lo into a plane at byte offset off
static __device__ __forceinline__ void st_split(char* smc, uint32_t plane, uint32_t off,
                                                float v0, float v1) {
    __half h0 = __float2half_rn(v0), h1 = __float2half_rn(v1);
    __half l0 = __float2half_rn(v0 - __half2float(h0));
    __half l1 = __float2half_rn(v1 - __half2float(h1));
    *(__half2*)(smc + plane + off) = __halves2half2(h0, h1);
    *(__half2*)(smc + plane + PL_LO + off) = __halves2half2(l0, l1);
}

// ---------------- main fused kernel ----------------
__global__ __launch_bounds__(THREADS, 1)
void lista_main(const float* __restrict__ y,
                const float* __restrict__ etas,
                const float* __restrict__ gammas,
                float* __restrict__ out) {
    extern __shared__ char smc[];
    const int tid = threadIdx.x, lane = tid & 31, wid = tid >> 5;
    const long b0 = (long)blockIdx.x * NB;

    // stage y: yr -> XR, yi -> XI, yr+yi -> XS (k rows 0..127)
    const float2* y2 = (const float2*)y;
    for (int idx = tid; idx < NB * 128; idx += THREADS) {
        const int n = idx >> 7, q = idx & 127;
        const float2 v = y2[(b0 + n) * 128 + q];
        const uint32_t off = swz64(q, n * 2);
        // single-element writes (split per element)
        __half hr = __float2half_rn(v.x);
        __half hi = __float2half_rn(v.y);
        float s = v.x + v.y;
        __half hs = __float2half_rn(s);
        *(__half*)(smc + XR_OFF + off) = hr;
        *(__half*)(smc + XR_OFF + PL_LO + off) = __float2half_rn(v.x - __half2float(hr));
        *(__half*)(smc + XI_OFF + off) = hi;
        *(__half*)(smc + XI_OFF + PL_LO + off) = __float2half_rn(v.y - __half2float(hi));
        *(__half*)(smc + XS_OFF + off) = hs;
        *(__half*)(smc + XS_OFF + PL_LO + off) = __float2half_rn(s - __half2float(hs));
    }
    __syncthreads();

    // lane geometry (epilogue/combine)
    const int eg = lane >> 2, ec = lane & 3;
    const uint32_t exor = (uint32_t)((eg & 6) << 3);

    const uint32_t s1plane = (wid < 8) ? XS_OFF : XI_OFF;
    const int gmt0 = 2 * wid;        // sub1 mtiles
    const int gmt2 = 32 + wid;       // sub2 mtile

    float d[8][4];     // sub1 accs
    float d2[4][4];    // sub2 accs (k3)

#pragma unroll 1
    for (int t = 0; t <= TT; ++t) {
        const __half* WH = t ? g_WBH : g_WAH;
        const __half* WL = t ? g_WBL : g_WAL;
        const int NC = t ? 16 : 8;

        // sub1: k1 (warps 0-7) / k2 (warps 8-15)
        gemm_sub<2>(smc, s1plane, WH, WL, NC, d, gmt0, lane);
        // store k1/k2 to kbuf (consumed after the sync)
        {
            const uint32_t kb = (wid < 8) ? K1_OFF : K2_OFF;
#pragma unroll
            for (int mt = 0; mt < 2; ++mt)
#pragma unroll
                for (int nt = 0; nt < 4; ++nt)
#pragma unroll
                    for (int rg = 0; rg < 2; ++rg) {
                        const int m = ((gmt0 + mt) & 15) * 16 + eg + rg * 8;
                        const uint32_t w = (uint32_t)m * 32 + scol(m, nt * 8 + ec * 2);
                        *(float2*)(smc + kb + w * 4) =
                            make_float2(d[mt * 4 + nt][rg * 2], d[mt * 4 + nt][rg * 2 + 1]);
                    }
        }
        // sub2: k3 (all warps, xr plane)
        gemm_sub<1>(smc, XR_OFF, WH, WL, NC, d2, gmt2, lane);
        __syncthreads();   // kbuf visible; all plane reads complete

        // combine + LISTA update: warp owns m in [16*wid, 16*wid+16)
        const float g = gammas[t], e = etas[t];
#pragma unroll
        for (int nt = 0; nt < 4; ++nt)
#pragma unroll
            for (int rg = 0; rg < 2; ++rg) {
                const int m = 16 * wid + eg + rg * 8;
                const int n0 = nt * 8 + ec * 2;
                const uint32_t w = (uint32_t)m * 32 + scol(m, n0);
                const float2 k1v = *(const float2*)(smc + K1_OFF + w * 4);
                const float2 k2v = *(const float2*)(smc + K2_OFF + w * 4);
                const float k3a = d2[nt][rg * 2 + 0], k3b = d2[nt][rg * 2 + 1];
                const float bre0 = k1v.x - k2v.x, bre1 = k1v.y - k2v.y;
                const float bim0 = k1v.x + k3a,  bim1 = k1v.y + k3b;
                float vre0, vre1, vim0, vim1;
                if (t == 0) {
                    *(float2*)(smc + AYR_OFF + w * 4) = make_float2(bre0, bre1);
                    *(float2*)(smc + AYI_OFF + w * 4) = make_float2(bim0, bim1);
                    vre0 = g * bre0; vre1 = g * bre1;
                    vim0 = g * bim0; vim1 = g * bim1;
                } else {
                    const float2 ar = *(const float2*)(smc + AYR_OFF + w * 4);
                    const float2 ai = *(const float2*)(smc + AYI_OFF + w * 4);
                    const uint32_t off = swz64(m, n0 * 2);
                    __half2 xrh = *(const __half2*)(smc + XR_OFF + off);
                    __half2 xrl = *(const __half2*)(smc + XR_OFF + PL_LO + off);
                    __half2 xih = *(const __half2*)(smc + XI_OFF + off);
                    __half2 xil = *(const __half2*)(smc + XI_OFF + PL_LO + off);
                    float2 fr = __half22float2(xrh), frl = __half22float2(xrl);
                    float2 fi = __half22float2(xih), fil = __half22float2(xil);
                    vre0 = fmaf(g, ar.x - bre0, fr.x + frl.x);
                    vre1 = fmaf(g, ar.y - bre1, fr.y + frl.y);
                    vim0 = fmaf(g, ai.x - bim0, fi.x + fil.x);
                    vim1 = fmaf(g, ai.y - bim1, fi.y + fil.y);
                }
                const float xr0 = copysignf(fmaxf(fabsf(vre0) - e, 0.0f), vre0);
                const float xr1 = copysignf(fmaxf(fabsf(vre1) - e, 0.0f), vre1);
                const float xi0 = copysignf(fmaxf(fabsf(vim0) - e, 0.0f), vim0);
                const float xi1 = copysignf(fmaxf(fabsf(vim1) - e, 0.0f), vim1);
                const uint32_t off = swz64(m, n0 * 2);
                st_split(smc, XR_OFF, off, xr0, xr1);
                st_split(smc, XI_OFF, off, xi0, xi1);
                st_split(smc, XS_OFF, off, xr0 + xi0, xr1 + xi1);
            }
        __syncthreads();
    }

    // output: out[b][m][c], re from XR, im from XI (hi + lo)
    for (int idx = tid; idx < NB * 512; idx += THREADS) {
        const int n = idx >> 9, i = idx & 511, m = i >> 1, cc = i & 1;
        const uint32_t pl = cc ? XI_OFF : XR_OFF;
        const uint32_t off = swz64(m, n * 2);
        const float v = __half2float(*(const __half*)(smc + pl + off))
                      + __half2float(*(const __half*)(smc + pl + PL_LO + off));
        out[(b0 + n) * 512 + i] = v;
    }
}

extern "C" void kernel_launch(void* const* d_in, const int* in_sizes, int n_in,
                              void* d_out, int out_size) {
    const float* y      = (const float*)d_in[0];
    const float* A      = (const float*)d_in[1];
    const float* B      = (const float*)d_in[2];
    const float* etas   = (const float*)d_in[3];
    const float* gammas = (const float*)d_in[4];
    float* out = (float*)d_out;

    prep_kernel<<<576, 512>>>(A, B);

    cudaFuncSetAttribute(lista_main, cudaFuncAttributeMaxDynamicSharedMemorySize, SMEM_TOTAL);
    lista_main<<<NCTA, THREADS, SMEM_TOTAL>>>(y, etas, gammas, out);
}

// round 11
// speedup vs baseline: 1.6272x; 1.2350x over previous
#include <cuda_runtime.h>
#include <cuda_fp16.h>
#include <cstdint>

#define TT        10
#define NB        32
#define THREADS   512
#define NCTA      (65536 / NB)       // 2048

// smem layout (bytes)
#define XSH_OFF   0                  // hi planes: 256 k-rows x 32 n x 2B = 16KB each
#define XIH_OFF   16384
#define XRH_OFF   32768
#define XRL_OFF   49152              // state lo planes (xr, xi)
#define XIL_OFF   65536
#define KB1_OFF   81920              // k1: 256 x 32 fp32 (scol-shifted)
#define KB2_OFF   114688             // k2
#define YSL_OFF   131072             // pass-0 ys-lo, aliased into upper half of KB2
#define AYR_OFF   147456             // Ay fp32
#define AYI_OFF   180224
#define SMEM_TOTAL 212992            // 208KB

// Gauss-stacked weights, MMA fragment order (same as R10):
// uint4 index ((chunk16*48 + gmt)*32 + lane); gmt [0,48): m 0-255 Br, 256-511 Br+Bi, 512-767 Bi-Br
__device__ __half g_WBH[196608];   // 384KB (16 chunks x 48 mtiles)
__device__ __half g_WBL[196608];
__device__ __half g_WAH[98304];    // 192KB (8 chunks x 48 mtiles)
__device__ __half g_WAL[98304];

// ---------------- PTX helpers ----------------
static __device__ __forceinline__ uint32_t smem_u32(const void* p) {
    uint32_t a;
    asm("{ .reg .u64 t; cvta.to.shared.u64 t, %1; cvt.u32.u64 %0, t; }" : "=r"(a) : "l"(p));
    return a;
}
static __device__ __forceinline__ void ldmB4(uint32_t* r, uint32_t addr) {
    asm volatile("ldmatrix.sync.aligned.m8n8.x4.trans.shared.b16 {%0,%1,%2,%3}, [%4];"
                 : "=r"(r[0]), "=r"(r[1]), "=r"(r[2]), "=r"(r[3]) : "r"(addr));
}
static __device__ __forceinline__ void mma16816(float* d, const uint32_t* a, const uint32_t* b) {
    asm volatile("mma.sync.aligned.m16n8k16.row.col.f32.f16.f16.f32 "
                 "{%0,%1,%2,%3}, {%4,%5,%6,%7}, {%8,%9}, {%0,%1,%2,%3};"
                 : "+f"(d[0]), "+f"(d[1]), "+f"(d[2]), "+f"(d[3])
                 : "r"(a[0]), "r"(a[1]), "r"(a[2]), "r"(a[3]), "r"(b[0]), "r"(b[1]));
}
// Swizzle for 64B rows (hi/lo planes)
static __device__ __host__ __forceinline__ uint32_t swz64(int row, int colbyte) {
    return (uint32_t)(row * 64 + (colbyte ^ ((row & 6) << 3)));
}
// fp32 scratch column shift: word index within a 32-word row
static __device__ __forceinline__ uint32_t scol(int m, int n0) {
    return (uint32_t)((n0 + ((m & 3) << 3)) & 31);
}

// ---------------- prep: Gauss-stacked W', fp16 hi/lo fragment order (unchanged) ----------------
__global__ void prep_kernel(const float* __restrict__ A, const float* __restrict__ B) {
    const int NBEL = 768 * 256, NAEL = 768 * 128;
    for (int i = blockIdx.x * blockDim.x + threadIdx.x; i < NBEL + NAEL;
         i += gridDim.x * blockDim.x) {
        int R, k;
        float w;
        __half *dH, *dL;
        if (i < NBEL) {
            R = i >> 8; k = i & 255;
            const int grp = R >> 8, m = R & 255;
            const float br = B[m * 256 + k], bi = B[65536 + m * 256 + k];
            w = (grp == 0) ? br : ((grp == 1) ? br + bi : bi - br);
            dH = g_WBH; dL = g_WBL;
        } else {
            const int j = i - NBEL;
            R = j >> 7; k = j & 127;
            const int grp = R >> 8, m = R & 255;
            const float ar = A[m * 128 + k], ai = A[32768 + m * 128 + k];
            w = (grp == 0) ? ar : ((grp == 1) ? ar + ai : ai - ar);
            dH = g_WAH; dL = g_WAL;
        }
        const int gmt = R >> 4, row = R & 15, chunk = k >> 4, kk = k & 15;
        const int rr = (row >> 3) | ((kk >> 3) << 1);
        const int t = (kk & 7) >> 1, pos = kk & 1;
        const int lane = (row & 7) * 4 + t;
        const int dest = ((chunk * 48 + gmt) * 32 + lane) * 8 + rr * 2 + pos;
        __half hi = __float2half_rn(w);
        dH[dest] = hi;
        dL[dest] = __float2half_rn(w - __half2float(hi));
    }
}

// ---------------- merged sweep: 3 mtiles/warp, one K-loop ----------------
// acc[12][4]: [0..7] = k1-or-k2 (gmtA, gmtA+1); [8..11] = k3 (gmt3)
static __device__ __forceinline__ void sweep(
    const char* smc, const __half* gHh, const __half* gLh, int NC, bool term3,
    uint32_t p1hi, uint32_t p1lo, float (*acc)[4], int gmtA, int gmt3, int lane)
{
    const uint4* gH = (const uint4*)gHh;
    const uint4* gL = (const uint4*)gLh;
    const uint32_t smb = smem_u32(smc);
    const uint32_t bxor = (uint32_t)((lane & 6) << 3);
    const uint32_t brow = ((uint32_t)(lane & 7) + ((uint32_t)((lane >> 3) & 1)) * 8) * 64;
    const uint32_t bcol0 = (((uint32_t)(lane >> 4) * 16)) ^ bxor;
    const uint32_t bcol1 = (32u + (uint32_t)(lane >> 4) * 16) ^ bxor;
    const int CS = 48 * 32;

#pragma unroll
    for (int i = 0; i < 12; ++i)
#pragma unroll
        for (int j = 0; j < 4; ++j) acc[i][j] = 0.0f;

    const int iA = gmtA * 32 + lane, i3 = gmt3 * 32 + lane;
    uint4 A0[6], A1[6];
    A0[0] = __ldg(gH + iA); A0[1] = __ldg(gH + iA + 32); A0[2] = __ldg(gH + i3);
    A0[3] = __ldg(gL + iA); A0[4] = __ldg(gL + iA + 32); A0[5] = __ldg(gL + i3);
    A1[0] = __ldg(gH + iA + CS); A1[1] = __ldg(gH + iA + CS + 32); A1[2] = __ldg(gH + i3 + CS);
    A1[3] = __ldg(gL + iA + CS); A1[4] = __ldg(gL + iA + CS + 32); A1[5] = __ldg(gL + i3 + CS);

#pragma unroll 1
    for (int c = 0; c < NC; c += 2) {
#pragma unroll
        for (int half = 0; half < 2; ++half) {
            const uint4* Ar = half ? A1 : A0;
            const uint32_t co = (uint32_t)(c + half) << 10;
            // ---- plane 1 (k1 or k2 operand) ----
            {
                uint32_t bh[8];
                ldmB4(bh,     smb + p1hi + co + brow + bcol0);
                ldmB4(bh + 4, smb + p1hi + co + brow + bcol1);
#pragma unroll
                for (int nt = 0; nt < 4; ++nt) {
                    mma16816(acc[nt],     (const uint32_t*)&Ar[0], &bh[nt * 2]); // Wh*xh
                    mma16816(acc[4 + nt], (const uint32_t*)&Ar[1], &bh[nt * 2]);
                }
#pragma unroll
                for (int nt = 0; nt < 4; ++nt) {
                    mma16816(acc[nt],     (const uint32_t*)&Ar[3], &bh[nt * 2]); // Wl*xh
                    mma16816(acc[4 + nt], (const uint32_t*)&Ar[4], &bh[nt * 2]);
                }
                if (term3) {
                    uint32_t bl[8];
                    ldmB4(bl,     smb + p1lo + co + brow + bcol0);
                    ldmB4(bl + 4, smb + p1lo + co + brow + bcol1);
#pragma unroll
                    for (int nt = 0; nt < 4; ++nt) {
                        mma16816(acc[nt],     (const uint32_t*)&Ar[0], &bl[nt * 2]); // Wh*xl
                        mma16816(acc[4 + nt], (const uint32_t*)&Ar[1], &bl[nt * 2]);
                    }
                }
            }
            // ---- plane 3 (xr, k3 operand) ----
            {
                uint32_t b3[8];
                ldmB4(b3,     smb + XRH_OFF + co + brow + bcol0);
                ldmB4(b3 + 4, smb + XRH_OFF + co + brow + bcol1);
#pragma unroll
                for (int nt = 0; nt < 4; ++nt)
                    mma16816(acc[8 + nt], (const uint32_t*)&Ar[2], &b3[nt * 2]);
#pragma unroll
                for (int nt = 0; nt < 4; ++nt)
                    mma16816(acc[8 + nt], (const uint32_t*)&Ar[5], &b3[nt * 2]);
                if (term3) {
                    uint32_t b3l[8];
                    ldmB4(b3l,     smb + XRL_OFF + co + brow + bcol0);
                    ldmB4(b3l + 4, smb + XRL_OFF + co + brow + bcol1);
#pragma unroll
                    for (int nt = 0; nt < 4; ++nt)
                        mma16816(acc[8 + nt], (const uint32_t*)&Ar[2], &b3l[nt * 2]);
                }
            }
            // prefetch this buffer's next chunk
            const int pf = c + half + 2;
            if (pf < NC) {
                uint4* Aw = half ? A1 : A0;
                Aw[0] = __ldg(gH + iA + pf * CS); Aw[1] = __ldg(gH + iA + pf * CS + 32);
                Aw[2] = __ldg(gH + i3 + pf * CS);
                Aw[3] = __ldg(gL + iA + pf * CS); Aw[4] = __ldg(gL + iA + pf * CS + 32);
                Aw[5] = __ldg(gL + i3 + pf * CS);
            }
        }
    }
}

// ---------------- main fused kernel ----------------
__global__ __launch_bounds__(THREADS, 1)
void lista_main(const float* __restrict__ y,
                const float* __restrict__ etas,
                const float* __restrict__ gammas,
                float* __restrict__ out) {
    extern __shared__ char smc[];
    const int tid = threadIdx.x, lane = tid & 31, wid = tid >> 5;
    const long b0 = (long)blockIdx.x * NB;

    // stage y: yr -> XRH/XRL, yi -> XIH/XIL, yr+yi -> XSH + YSL(lo)
    const float2* y2 = (const float2*)y;
    for (int idx = tid; idx < NB * 128; idx += THREADS) {
        const int n = idx >> 7, q = idx & 127;
        const float2 v = y2[(b0 + n) * 128 + q];
        const uint32_t off = swz64(q, n * 2);
        __half hr = __float2half_rn(v.x);
        __half hi = __float2half_rn(v.y);
        const float s = v.x + v.y;
        __half hs = __float2half_rn(s);
        *(__half*)(smc + XRH_OFF + off) = hr;
        *(__half*)(smc + XRL_OFF + off) = __float2half_rn(v.x - __half2float(hr));
        *(__half*)(smc + XIH_OFF + off) = hi;
        *(__half*)(smc + XIL_OFF + off) = __float2half_rn(v.y - __half2float(hi));
        *(__half*)(smc + XSH_OFF + off) = hs;
        *(__half*)(smc + YSL_OFF + off) = __float2half_rn(s - __half2float(hs));
    }
    __syncthreads();

    // lane geometry
    const int eg = lane >> 2, ec = lane & 3;

    const uint32_t p1hi = (wid < 8) ? XSH_OFF : XIH_OFF;
    const int gmtA = 2 * wid;        // k1/k2 mtile pair
    const int gmt3 = 32 + wid;       // k3 mtile

    float acc[12][4];

#pragma unroll 1
    for (int t = 0; t <= TT; ++t) {
        const bool t3 = (t == 0);
        const __half* WH = t ? g_WBH : g_WAH;
        const __half* WL = t ? g_WBL : g_WAL;
        const int NC = t ? 16 : 8;
        const uint32_t p1lo = (wid < 8) ? YSL_OFF : XIL_OFF;

        sweep(smc, WH, WL, NC, t3, p1hi, p1lo, acc, gmtA, gmt3, lane);

        if (t == 0) __syncthreads();   // YSL alias: all sweep reads done before kbuf store

        // store k1/k2 to kbuf
        {
            const uint32_t kb = (wid < 8) ? KB1_OFF : KB2_OFF;
            const int mb = (wid < 8) ? 32 * wid : 32 * (wid - 8);
#pragma unroll
            for (int mt = 0; mt < 2; ++mt)
#pragma unroll
                for (int nt = 0; nt < 4; ++nt)
#pragma unroll
                    for (int rg = 0; rg < 2; ++rg) {
                        const int m = mb + 16 * mt + eg + 8 * rg;
                        const uint32_t w = (uint32_t)m * 32 + scol(m, nt * 8 + ec * 2);
                        *(float2*)(smc + kb + w * 4) =
                            make_float2(acc[mt * 4 + nt][rg * 2], acc[mt * 4 + nt][rg * 2 + 1]);
                    }
        }
        __syncthreads();

        // combine + LISTA update: warp owns m in [16*wid, 16*wid+16)
        const float g = gammas[t], e = etas[t];
#pragma unroll
        for (int nt = 0; nt < 4; ++nt)
#pragma unroll
            for (int rg = 0; rg < 2; ++rg) {
                const int m = 16 * wid + eg + rg * 8;
                const int n0 = nt * 8 + ec * 2;
                const uint32_t w = (uint32_t)m * 32 + scol(m, n0);
                const float2 k1v = *(const float2*)(smc + KB1_OFF + w * 4);
                const float2 k2v = *(const float2*)(smc + KB2_OFF + w * 4);
                const float k3a = acc[8 + nt][rg * 2 + 0], k3b = acc[8 + nt][rg * 2 + 1];
                const float bre0 = k1v.x - k2v.x, bre1 = k1v.y - k2v.y;
                const float bim0 = k1v.x + k3a,  bim1 = k1v.y + k3b;
                const uint32_t off = swz64(m, n0 * 2);
                float vre0, vre1, vim0, vim1;
                if (t == 0) {
                    *(float2*)(smc + AYR_OFF + w * 4) = make_float2(bre0, bre1);
                    *(float2*)(smc + AYI_OFF + w * 4) = make_float2(bim0, bim1);
                    vre0 = g * bre0; vre1 = g * bre1;
                    vim0 = g * bim0; vim1 = g * bim1;
                } else {
                    const float2 ar = *(const float2*)(smc + AYR_OFF + w * 4);
                    const float2 ai = *(const float2*)(smc + AYI_OFF + w * 4);
                    float2 fr  = __half22float2(*(const __half2*)(smc + XRH_OFF + off));
                    float2 frl = __half22float2(*(const __half2*)(smc + XRL_OFF + off));
                    float2 fi  = __half22float2(*(const __half2*)(smc + XIH_OFF + off));
                    float2 fil = __half22float2(*(const __half2*)(smc + XIL_OFF + off));
                    vre0 = fmaf(g, ar.x - bre0, fr.x + frl.x);
                    vre1 = fmaf(g, ar.y - bre1, fr.y + frl.y);
                    vim0 = fmaf(g, ai.x - bim0, fi.x + fil.x);
                    vim1 = fmaf(g, ai.y - bim1, fi.y + fil.y);
                }
                const float xr0 = copysignf(fmaxf(fabsf(vre0) - e, 0.0f), vre0);
                const float xr1 = copysignf(fmaxf(fabsf(vre1) - e, 0.0f), vre1);
                const float xi0 = copysignf(fmaxf(fabsf(vim0) - e, 0.0f), vim0);
                const float xi1 = copysignf(fmaxf(fabsf(vim1) - e, 0.0f), vim1);
                // state hi/lo (xr, xi)
                __half h0 = __float2half_rn(xr0), h1 = __float2half_rn(xr1);
                *(__half2*)(smc + XRH_OFF + off) = __halves2half2(h0, h1);
                *(__half2*)(smc + XRL_OFF + off) = __halves2half2(
                    __float2half_rn(xr0 - __half2float(h0)),
                    __float2half_rn(xr1 - __half2float(h1)));
                __half g0 = __float2half_rn(xi0), g1 = __float2half_rn(xi1);
                *(__half2*)(smc + XIH_OFF + off) = __halves2half2(g0, g1);
                *(__half2*)(smc + XIL_OFF + off) = __halves2half2(
                    __float2half_rn(xi0 - __half2float(g0)),
                    __float2half_rn(xi1 - __half2float(g1)));
                // xs hi (MMA operand only)
                *(__half2*)(smc + XSH_OFF + off) = __halves2half2(
                    __float2half_rn(xr0 + xi0), __float2half_rn(xr1 + xi1));
            }
        __syncthreads();
    }

    // output: out[b][m][c], re = XRH+XRL, im = XIH+XIL
    for (int idx = tid; idx < NB * 512; idx += THREADS) {
        const int n = idx >> 9, i = idx & 511, m = i >> 1, cc = i & 1;
        const uint32_t ph = cc ? XIH_OFF : XRH_OFF;
        const uint32_t pl = cc ? XIL_OFF : XRL_OFF;
        const uint32_t off = swz64(m, n * 2);
        const float v = __half2float(*(const __half*)(smc + ph + off))
                      + __half2float(*(const __half*)(smc + pl + off));
        out[(b0 + n) * 512 + i] = v;
    }
}

extern "C" void kernel_launch(void* const* d_in, const int* in_sizes, int n_in,
                              void* d_out, int out_size) {
    const float* y      = (const float*)d_in[0];
    const float* A      = (const float*)d_in[1];
    const float* B      = (const float*)d_in[2];
    const float* etas   = (const float*)d_in[3];
    const float* gammas = (const float*)d_in[4];
    float* out = (float*)d_out;

    prep_kernel<<<576, 512>>>(A, B);

    cudaFuncSetAttribute(lista_main, cudaFuncAttributeMaxDynamicSharedMemorySize, SMEM_TOTAL);
    lista_main<<<NCTA, THREADS, SMEM_TOTAL>>>(y, etas, gammas, out);
}